// round 14
// baseline (speedup 1.0000x reference)
#include <cuda_runtime.h>
#include <cuda_fp16.h>

// Problem constants
#define BATCH 128
#define NIN   1152
#define DIN   8
#define NOUT  10
#define DDIM  16
#define FDIM  160
#define NTRI  (NIN / 3)          // 384 i-triples
#define TRIH  512                // halves per triple block (960 used + 64 pad)
#define ROWH  ((size_t)NTRI * TRIH)
#define SQ_EPS 1e-7f

#define K2_THREADS 1024
#define K2_WARPS   32
#define K2_ITERS   12            // triples per warp (12*32 = 384)

typedef unsigned long long ull;

// u_hat scratch, i-triple-blocked layout:
//   half index = ((b*NTRI + t)*TRIH) + q*256 + lane*8 + h
//   lane = (i%3)*10 + j (0..29; 30,31 pad), q = d/8, h = d%8
__device__ __half g_uhat[(size_t)BATCH * ROWH];

// ---------------- packed f32x2 helpers -------------------------------------
__device__ __forceinline__ ull pk2(float lo, float hi) {
    ull r; asm("mov.b64 %0, {%1, %2};" : "=l"(r) : "f"(lo), "f"(hi)); return r;
}
__device__ __forceinline__ void upk2(ull v, float& lo, float& hi) {
    asm("mov.b64 {%0, %1}, %2;" : "=f"(lo), "=f"(hi) : "l"(v));
}
__device__ __forceinline__ ull fma2(ull a, ull b, ull c) {
    ull d; asm("fma.rn.f32x2 %0, %1, %2, %3;" : "=l"(d) : "l"(a), "l"(b), "l"(c)); return d;
}
__device__ __forceinline__ ull mul2(ull a, ull b) {
    ull d; asm("mul.rn.f32x2 %0, %1, %2;" : "=l"(d) : "l"(a), "l"(b)); return d;
}
__device__ __forceinline__ ull add2(ull a, ull b) {
    ull d; asm("add.rn.f32x2 %0, %1, %2;" : "=l"(d) : "l"(a), "l"(b)); return d;
}
__device__ __forceinline__ ull h2_to_f2(unsigned h2) {
    ull r;
    asm("{\n\t"
        ".reg .b16 l, h;\n\t"
        ".reg .f32 fl, fh;\n\t"
        "mov.b32 {l, h}, %1;\n\t"
        "cvt.f32.f16 fl, l;\n\t"
        "cvt.f32.f16 fh, h;\n\t"
        "mov.b64 %0, {fl, fh};\n\t"
        "}" : "=l"(r) : "r"(h2));
    return r;
}

// ---------------------------------------------------------------------------
// K1: u_hat[b,i,f] = sum_k W[i,f,k] * x[b,i,k]  -> fp16, triple-blocked store.
// One block per i; thread owns an f-pair (same j, consecutive d's, same q).
// (EXACT R7 kernel — best measured k1; do not modify)
// ---------------------------------------------------------------------------
__global__ __launch_bounds__(320) void k1_uhat(const float* __restrict__ x,
                                               const float* __restrict__ W) {
    const int i = blockIdx.x;                 // 0..1151
    const int t = i / 3;
    const int g = i % 3;
    __shared__ __align__(16) float Ws[FDIM * DIN];   // 5 KB
    __shared__ __align__(16) float xs[BATCH * DIN];  // 4 KB
    const int tid = threadIdx.x;

    for (int tt = tid; tt < FDIM * DIN; tt += 320)
        Ws[tt] = W[(size_t)i * (FDIM * DIN) + tt];
    for (int tt = tid; tt < BATCH * DIN; tt += 320) {
        const int b = tt / DIN, k = tt % DIN;
        xs[tt] = x[((size_t)b * NIN + i) * DIN + k];
    }
    __syncthreads();

    const int f2 = tid % 80;
    const int b0 = tid / 80;
    const int j  = f2 / 8;
    const int dA = (f2 % 8) * 2;
    const int q  = dA >> 3;
    const int hh = dA & 7;

    float wA[DIN], wB[DIN];
#pragma unroll
    for (int k = 0; k < DIN; k++) {
        wA[k] = Ws[(2 * f2) * DIN + k];
        wB[k] = Ws[(2 * f2 + 1) * DIN + k];
    }

    const size_t slot_h2 = ((size_t)t * TRIH + q * 256 + (g * 10 + j) * 8 + hh) / 2;
    __half2* __restrict__ uh2 = reinterpret_cast<__half2*>(g_uhat) + slot_h2;

    for (int b = b0; b < BATCH; b += 4) {
        const float4 xa = *reinterpret_cast<const float4*>(&xs[b * DIN]);
        const float4 xb = *reinterpret_cast<const float4*>(&xs[b * DIN + 4]);
        float a0 = wA[0] * xa.x, a1 = wB[0] * xa.x;
        a0 = fmaf(wA[1], xa.y, a0);  a1 = fmaf(wB[1], xa.y, a1);
        a0 = fmaf(wA[2], xa.z, a0);  a1 = fmaf(wB[2], xa.z, a1);
        a0 = fmaf(wA[3], xa.w, a0);  a1 = fmaf(wB[3], xa.w, a1);
        a0 = fmaf(wA[4], xb.x, a0);  a1 = fmaf(wB[4], xb.x, a1);
        a0 = fmaf(wA[5], xb.y, a0);  a1 = fmaf(wB[5], xb.y, a1);
        a0 = fmaf(wA[6], xb.z, a0);  a1 = fmaf(wB[6], xb.z, a1);
        a0 = fmaf(wA[7], xb.w, a0);  a1 = fmaf(wB[7], xb.w, a1);
        uh2[(size_t)b * (ROWH / 2)] = __floats2half2_rn(a0, a1);
    }
}

// ---------------------------------------------------------------------------
// K2: fused 3-iteration dynamic routing, one block (1024 thr, 32 warps) per b.
// TLP-based latency hiding (no explicit prefetch; 64-reg budget).
// ---------------------------------------------------------------------------
__global__ __launch_bounds__(K2_THREADS, 1) void k2_route(const float* __restrict__ bias,
                                                          float* __restrict__ out) {
    const int b   = blockIdx.x;
    const int tid = threadIdx.x;
    const int w   = tid >> 5;
    const int l   = tid & 31;
    const bool active = (l < 30);
    const int g = active ? (l / 10) : 0;
    const int j = active ? (l % 10) : 0;

    __shared__ float s_part[K2_WARPS][FDIM];  // 20 KB
    __shared__ float s_red[FDIM];
    __shared__ float vsum_sm[FDIM];
    __shared__ float vlast_sm[FDIM];
    __shared__ float bias_sm[FDIM];

    if (tid < FDIM) bias_sm[tid] = bias[tid];

    const uint4* __restrict__ ubase4 =
        reinterpret_cast<const uint4*>(g_uhat + (size_t)b * ROWH);
    const unsigned FULL = 0xFFFFFFFFu;

    for (int pass = 0; pass < 3; ++pass) {
        ull vr2[8];
        if (pass > 0) {
#pragma unroll
            for (int m = 0; m < 8; m++)
                vr2[m] = pk2(vsum_sm[j * DDIM + 2 * m], vsum_sm[j * DDIM + 2 * m + 1]);
        }
        ull sacc2[8];
#pragma unroll
        for (int m = 0; m < 8; m++) sacc2[m] = 0ull;

#pragma unroll 2
        for (int it = 0; it < K2_ITERS; ++it) {
            const uint4* up = ubase4 + (size_t)(w * K2_ITERS + it) * 64 + l;
            const uint4 p0 = up[0];
            const uint4 p1 = up[32];

            ull u2[8];
            u2[0] = h2_to_f2(p0.x); u2[1] = h2_to_f2(p0.y);
            u2[2] = h2_to_f2(p0.z); u2[3] = h2_to_f2(p0.w);
            u2[4] = h2_to_f2(p1.x); u2[5] = h2_to_f2(p1.y);
            u2[6] = h2_to_f2(p1.z); u2[7] = h2_to_f2(p1.w);

            if (pass == 0) {
#pragma unroll
                for (int m = 0; m < 8; m++) sacc2[m] = add2(sacc2[m], u2[m]);
            } else {
                ull a2a = mul2(u2[0], vr2[0]);
                ull a2b = mul2(u2[1], vr2[1]);
                a2a = fma2(u2[2], vr2[2], a2a);
                a2b = fma2(u2[3], vr2[3], a2b);
                a2a = fma2(u2[4], vr2[4], a2a);
                a2b = fma2(u2[5], vr2[5], a2b);
                a2a = fma2(u2[6], vr2[6], a2a);
                a2b = fma2(u2[7], vr2[7], a2b);
                const ull a2 = add2(a2a, a2b);
                float alo, ahi; upk2(a2, alo, ahi);
                float a = alo + ahi;
                a = fmaxf(fminf(a, 60.f), -60.f);   // garbage-safe clamp
                const float e = __expf(a);
                float ev[NOUT];
#pragma unroll
                for (int jj = 0; jj < NOUT; jj++)
                    ev[jj] = __shfl_sync(FULL, e, g * 10 + jj);
                const float s01 = ev[0] + ev[1];
                const float s23 = ev[2] + ev[3];
                const float s45 = ev[4] + ev[5];
                const float s67 = ev[6] + ev[7];
                const float s89 = ev[8] + ev[9];
                const float esum = ((s01 + s23) + (s45 + s67)) + s89;
                const float c = __fdividef(e, esum);
                const ull c2 = pk2(c, c);
#pragma unroll
                for (int m = 0; m < 8; m++) sacc2[m] = fma2(c2, u2[m], sacc2[m]);
            }
        }

        // combine 3 groups (lanes l, l+10, l+20) -> lanes 0..9
#pragma unroll
        for (int m = 0; m < 8; m++) {
            const ull t1 = __shfl_down_sync(FULL, sacc2[m], 10);
            const ull t2 = __shfl_down_sync(FULL, sacc2[m], 20);
            sacc2[m] = add2(sacc2[m], add2(t1, t2));
        }
        if (l < NOUT) {
#pragma unroll
            for (int m = 0; m < 8; m++)
                *reinterpret_cast<ull*>(&s_part[w][l * DDIM + 2 * m]) = sacc2[m];
        }
        __syncthreads();

        if (tid < FDIM) {
            float acc = 0.f;
#pragma unroll
            for (int ww = 0; ww < K2_WARPS; ww++) acc += s_part[ww][tid];
            if (pass == 0) acc *= (1.0f / NOUT);
            s_red[tid] = acc + bias_sm[tid];
        }
        __syncthreads();

        if (tid < NOUT) {
            float sv[DDIM];
            float sq = 0.f;
#pragma unroll
            for (int d = 0; d < DDIM; d++) {
                sv[d] = s_red[tid * DDIM + d];
                sq = fmaf(sv[d], sv[d], sq);
            }
            const float scale = sq / (1.0f + sq) * rsqrtf(sq + SQ_EPS);
#pragma unroll
            for (int d = 0; d < DDIM; d++) {
                const float v = scale * sv[d];
                vlast_sm[tid * DDIM + d] = v;
                if (pass == 0)      vsum_sm[tid * DDIM + d] = v;
                else if (pass == 1) vsum_sm[tid * DDIM + d] += v;
            }
        }
        __syncthreads();
    }

    if (tid < FDIM) out[(size_t)b * FDIM + tid] = vlast_sm[tid];
}

// ---------------------------------------------------------------------------
extern "C" void kernel_launch(void* const* d_in, const int* in_sizes, int n_in,
                              void* d_out, int out_size) {
    const float* x = nullptr;
    const float* W = nullptr;
    const float* bias = nullptr;
    for (int idx = 0; idx < n_in; ++idx) {
        if (in_sizes[idx] == BATCH * NIN * DIN)             x    = (const float*)d_in[idx];
        else if (in_sizes[idx] == NIN * NOUT * DDIM * DIN)  W    = (const float*)d_in[idx];
        else if (in_sizes[idx] == NOUT * DDIM)              bias = (const float*)d_in[idx];
    }
    k1_uhat<<<NIN, 320>>>(x, W);
    k2_route<<<BATCH, K2_THREADS>>>(bias, (float*)d_out);
}

// round 15
// speedup vs baseline: 1.1446x; 1.1446x over previous
#include <cuda_runtime.h>
#include <cuda_fp16.h>

// Problem constants
#define BATCH 128
#define NIN   1152
#define DIN   8
#define NOUT  10
#define DDIM  16
#define FDIM  160
#define NTRI  (NIN / 3)          // 384 i-triples
#define TRIH  512                // halves per triple block (960 used + 64 pad)
#define ROWH  ((size_t)NTRI * TRIH)
#define SQ_EPS 1e-7f

#define K2_THREADS 768
#define K2_WARPS   24
#define K2_ITERS   16            // triples per warp

typedef unsigned long long ull;

// u_hat scratch, i-triple-blocked layout:
//   half index = ((b*NTRI + t)*TRIH) + q*256 + lane*8 + h
//   lane = (i%3)*10 + j (0..29; 30,31 pad), q = d/8, h = d%8
__device__ __half g_uhat[(size_t)BATCH * ROWH];

// ---------------- packed f32x2 / f16x2 helpers ------------------------------
__device__ __forceinline__ ull pk2(float lo, float hi) {
    ull r; asm("mov.b64 %0, {%1, %2};" : "=l"(r) : "f"(lo), "f"(hi)); return r;
}
__device__ __forceinline__ void upk2(ull v, float& lo, float& hi) {
    asm("mov.b64 {%0, %1}, %2;" : "=f"(lo), "=f"(hi) : "l"(v));
}
__device__ __forceinline__ ull fma2(ull a, ull b, ull c) {
    ull d; asm("fma.rn.f32x2 %0, %1, %2, %3;" : "=l"(d) : "l"(a), "l"(b), "l"(c)); return d;
}
__device__ __forceinline__ ull mul2(ull a, ull b) {
    ull d; asm("mul.rn.f32x2 %0, %1, %2;" : "=l"(d) : "l"(a), "l"(b)); return d;
}
__device__ __forceinline__ ull add2(ull a, ull b) {
    ull d; asm("add.rn.f32x2 %0, %1, %2;" : "=l"(d) : "l"(a), "l"(b)); return d;
}
__device__ __forceinline__ unsigned hadd2u(unsigned a, unsigned b) {
    unsigned d; asm("add.rn.f16x2 %0, %1, %2;" : "=r"(d) : "r"(a), "r"(b)); return d;
}
__device__ __forceinline__ ull h2_to_f2(unsigned h2) {
    ull r;
    asm("{\n\t"
        ".reg .b16 l, h;\n\t"
        ".reg .f32 fl, fh;\n\t"
        "mov.b32 {l, h}, %1;\n\t"
        "cvt.f32.f16 fl, l;\n\t"
        "cvt.f32.f16 fh, h;\n\t"
        "mov.b64 %0, {fl, fh};\n\t"
        "}" : "=l"(r) : "r"(h2));
    return r;
}

// ---------------------------------------------------------------------------
// K1: u_hat[b,i,f] = sum_k W[i,f,k] * x[b,i,k]  -> fp16, triple-blocked store.
// (EXACT R7 kernel — best measured k1; do not modify)
// ---------------------------------------------------------------------------
__global__ __launch_bounds__(320) void k1_uhat(const float* __restrict__ x,
                                               const float* __restrict__ W) {
    const int i = blockIdx.x;                 // 0..1151
    const int t = i / 3;
    const int g = i % 3;
    __shared__ __align__(16) float Ws[FDIM * DIN];   // 5 KB
    __shared__ __align__(16) float xs[BATCH * DIN];  // 4 KB
    const int tid = threadIdx.x;

    for (int tt = tid; tt < FDIM * DIN; tt += 320)
        Ws[tt] = W[(size_t)i * (FDIM * DIN) + tt];
    for (int tt = tid; tt < BATCH * DIN; tt += 320) {
        const int b = tt / DIN, k = tt % DIN;
        xs[tt] = x[((size_t)b * NIN + i) * DIN + k];
    }
    __syncthreads();

    const int f2 = tid % 80;
    const int b0 = tid / 80;
    const int j  = f2 / 8;
    const int dA = (f2 % 8) * 2;
    const int q  = dA >> 3;
    const int hh = dA & 7;

    float wA[DIN], wB[DIN];
#pragma unroll
    for (int k = 0; k < DIN; k++) {
        wA[k] = Ws[(2 * f2) * DIN + k];
        wB[k] = Ws[(2 * f2 + 1) * DIN + k];
    }

    const size_t slot_h2 = ((size_t)t * TRIH + q * 256 + (g * 10 + j) * 8 + hh) / 2;
    __half2* __restrict__ uh2 = reinterpret_cast<__half2*>(g_uhat) + slot_h2;

    for (int b = b0; b < BATCH; b += 4) {
        const float4 xa = *reinterpret_cast<const float4*>(&xs[b * DIN]);
        const float4 xb = *reinterpret_cast<const float4*>(&xs[b * DIN + 4]);
        float a0 = wA[0] * xa.x, a1 = wB[0] * xa.x;
        a0 = fmaf(wA[1], xa.y, a0);  a1 = fmaf(wB[1], xa.y, a1);
        a0 = fmaf(wA[2], xa.z, a0);  a1 = fmaf(wB[2], xa.z, a1);
        a0 = fmaf(wA[3], xa.w, a0);  a1 = fmaf(wB[3], xa.w, a1);
        a0 = fmaf(wA[4], xb.x, a0);  a1 = fmaf(wB[4], xb.x, a1);
        a0 = fmaf(wA[5], xb.y, a0);  a1 = fmaf(wB[5], xb.y, a1);
        a0 = fmaf(wA[6], xb.z, a0);  a1 = fmaf(wB[6], xb.z, a1);
        a0 = fmaf(wA[7], xb.w, a0);  a1 = fmaf(wB[7], xb.w, a1);
        uh2[(size_t)b * (ROWH / 2)] = __floats2half2_rn(a0, a1);
    }
}

// ---------------------------------------------------------------------------
// K2: fused 3-iteration dynamic routing, one block (768 thr) per b.
// Pass 0: fp16 HADD2 accumulation (dual accumulators), no per-iter cvt.
// Passes 1-2: slim group-local shuffle-down softmax reduction.
// ---------------------------------------------------------------------------
__global__ __launch_bounds__(K2_THREADS) void k2_route(const float* __restrict__ bias,
                                                       float* __restrict__ out) {
    const int b   = blockIdx.x;
    const int tid = threadIdx.x;
    const int w   = tid >> 5;
    const int l   = tid & 31;
    const bool active = (l < 30);
    const int g = active ? (l / 10) : 0;
    const int j = active ? (l % 10) : 0;
    const int leader = g * 10;

    __shared__ float s_part[K2_WARPS][FDIM];
    __shared__ float s_red[FDIM];
    __shared__ float vsum_sm[FDIM];
    __shared__ float vlast_sm[FDIM];
    __shared__ float bias_sm[FDIM];

    if (tid < FDIM) bias_sm[tid] = bias[tid];

    const uint4* __restrict__ ubase4 =
        reinterpret_cast<const uint4*>(g_uhat + (size_t)b * ROWH);
    const unsigned FULL = 0xFFFFFFFFu;

    // ================= pass 0: s0 = (1/10) * sum_i u + bias ================
    {
        unsigned ha[8], hb[8];
#pragma unroll
        for (int m = 0; m < 8; m++) { ha[m] = 0u; hb[m] = 0u; }

        uint4 p0, p1;
        {
            const uint4* up = ubase4 + (size_t)(w * K2_ITERS) * 64 + l;
            p0 = up[0];
            p1 = up[32];
        }
        for (int it = 0; it < K2_ITERS; ++it) {
            uint4 n0, n1;
            if (it + 1 < K2_ITERS) {
                const uint4* up = ubase4 + (size_t)(w * K2_ITERS + it + 1) * 64 + l;
                n0 = up[0];
                n1 = up[32];
            } else {
                n0 = p0; n1 = p1;
            }
            if ((it & 1) == 0) {
                ha[0] = hadd2u(ha[0], p0.x); ha[1] = hadd2u(ha[1], p0.y);
                ha[2] = hadd2u(ha[2], p0.z); ha[3] = hadd2u(ha[3], p0.w);
                ha[4] = hadd2u(ha[4], p1.x); ha[5] = hadd2u(ha[5], p1.y);
                ha[6] = hadd2u(ha[6], p1.z); ha[7] = hadd2u(ha[7], p1.w);
            } else {
                hb[0] = hadd2u(hb[0], p0.x); hb[1] = hadd2u(hb[1], p0.y);
                hb[2] = hadd2u(hb[2], p0.z); hb[3] = hadd2u(hb[3], p0.w);
                hb[4] = hadd2u(hb[4], p1.x); hb[5] = hadd2u(hb[5], p1.y);
                hb[6] = hadd2u(hb[6], p1.z); hb[7] = hadd2u(hb[7], p1.w);
            }
            p0 = n0; p1 = n1;
        }

        ull sacc2[8];
#pragma unroll
        for (int m = 0; m < 8; m++)
            sacc2[m] = add2(h2_to_f2(ha[m]), h2_to_f2(hb[m]));

        // combine 3 groups -> lanes 0..9
#pragma unroll
        for (int m = 0; m < 8; m++) {
            const ull t1 = __shfl_down_sync(FULL, sacc2[m], 10);
            const ull t2 = __shfl_down_sync(FULL, sacc2[m], 20);
            sacc2[m] = add2(sacc2[m], add2(t1, t2));
        }
        if (l < NOUT) {
#pragma unroll
            for (int m = 0; m < 8; m++)
                *reinterpret_cast<ull*>(&s_part[w][l * DDIM + 2 * m]) = sacc2[m];
        }
        __syncthreads();

        if (tid < FDIM) {
            float acc = 0.f;
#pragma unroll
            for (int ww = 0; ww < K2_WARPS; ww++) acc += s_part[ww][tid];
            s_red[tid] = acc * (1.0f / NOUT) + bias_sm[tid];
        }
        __syncthreads();

        if (tid < NOUT) {
            float sv[DDIM];
            float sq = 0.f;
#pragma unroll
            for (int d = 0; d < DDIM; d++) {
                sv[d] = s_red[tid * DDIM + d];
                sq = fmaf(sv[d], sv[d], sq);
            }
            const float scale = sq / (1.0f + sq) * rsqrtf(sq + SQ_EPS);
#pragma unroll
            for (int d = 0; d < DDIM; d++)
                vsum_sm[tid * DDIM + d] = scale * sv[d];   // v0
        }
        __syncthreads();
    }

    // ================= passes 1-2: routed accumulation =====================
    for (int pass = 1; pass < 3; ++pass) {
        ull vr2[8];
#pragma unroll
        for (int m = 0; m < 8; m++)
            vr2[m] = pk2(vsum_sm[j * DDIM + 2 * m], vsum_sm[j * DDIM + 2 * m + 1]);
        ull sacc2[8];
#pragma unroll
        for (int m = 0; m < 8; m++) sacc2[m] = 0ull;

        uint4 p0, p1;
        {
            const uint4* up = ubase4 + (size_t)(w * K2_ITERS) * 64 + l;
            p0 = up[0];
            p1 = up[32];
        }

        for (int it = 0; it < K2_ITERS; ++it) {
            uint4 n0, n1;
            if (it + 1 < K2_ITERS) {
                const uint4* up = ubase4 + (size_t)(w * K2_ITERS + it + 1) * 64 + l;
                n0 = up[0];
                n1 = up[32];
            } else {
                n0 = p0; n1 = p1;
            }

            ull u2[8];
            u2[0] = h2_to_f2(p0.x); u2[1] = h2_to_f2(p0.y);
            u2[2] = h2_to_f2(p0.z); u2[3] = h2_to_f2(p0.w);
            u2[4] = h2_to_f2(p1.x); u2[5] = h2_to_f2(p1.y);
            u2[6] = h2_to_f2(p1.z); u2[7] = h2_to_f2(p1.w);

            // logit: two independent 4-deep fma2 chains + combine
            ull a2a = mul2(u2[0], vr2[0]);
            ull a2b = mul2(u2[1], vr2[1]);
            a2a = fma2(u2[2], vr2[2], a2a);
            a2b = fma2(u2[3], vr2[3], a2b);
            a2a = fma2(u2[4], vr2[4], a2a);
            a2b = fma2(u2[5], vr2[5], a2b);
            a2a = fma2(u2[6], vr2[6], a2a);
            a2b = fma2(u2[7], vr2[7], a2b);
            const ull a2 = add2(a2a, a2b);
            float alo, ahi; upk2(a2, alo, ahi);
            float a = alo + ahi;
            a = fmaxf(fminf(a, 60.f), -60.f);        // garbage-safe clamp
            const float e = active ? __expf(a) : 0.f; // pad lanes contribute 0

            // group-local sum of 10 e's via shuffle-down tree
            const float p  = e + __shfl_down_sync(FULL, e, 5);
            const float qq = p + __shfl_down_sync(FULL, p, 2);
            const float r  = qq + __shfl_down_sync(FULL, qq, 1);
            const float es = r + __shfl_down_sync(FULL, p, 4);   // at leader
            const float esum = __shfl_sync(FULL, es, leader);
            const float c = __fdividef(e, esum);
            const ull c2 = pk2(c, c);
#pragma unroll
            for (int m = 0; m < 8; m++) sacc2[m] = fma2(c2, u2[m], sacc2[m]);

            p0 = n0; p1 = n1;
        }

        // combine 3 groups -> lanes 0..9
#pragma unroll
        for (int m = 0; m < 8; m++) {
            const ull t1 = __shfl_down_sync(FULL, sacc2[m], 10);
            const ull t2 = __shfl_down_sync(FULL, sacc2[m], 20);
            sacc2[m] = add2(sacc2[m], add2(t1, t2));
        }
        if (l < NOUT) {
#pragma unroll
            for (int m = 0; m < 8; m++)
                *reinterpret_cast<ull*>(&s_part[w][l * DDIM + 2 * m]) = sacc2[m];
        }
        __syncthreads();

        if (tid < FDIM) {
            float acc = 0.f;
#pragma unroll
            for (int ww = 0; ww < K2_WARPS; ww++) acc += s_part[ww][tid];
            s_red[tid] = acc + bias_sm[tid];
        }
        __syncthreads();

        if (tid < NOUT) {
            float sv[DDIM];
            float sq = 0.f;
#pragma unroll
            for (int d = 0; d < DDIM; d++) {
                sv[d] = s_red[tid * DDIM + d];
                sq = fmaf(sv[d], sv[d], sq);
            }
            const float scale = sq / (1.0f + sq) * rsqrtf(sq + SQ_EPS);
#pragma unroll
            for (int d = 0; d < DDIM; d++) {
                const float v = scale * sv[d];
                vlast_sm[tid * DDIM + d] = v;
                if (pass == 1) vsum_sm[tid * DDIM + d] += v;
            }
        }
        __syncthreads();
    }

    if (tid < FDIM) out[(size_t)b * FDIM + tid] = vlast_sm[tid];
}

// ---------------------------------------------------------------------------
extern "C" void kernel_launch(void* const* d_in, const int* in_sizes, int n_in,
                              void* d_out, int out_size) {
    const float* x = nullptr;
    const float* W = nullptr;
    const float* bias = nullptr;
    for (int idx = 0; idx < n_in; ++idx) {
        if (in_sizes[idx] == BATCH * NIN * DIN)             x    = (const float*)d_in[idx];
        else if (in_sizes[idx] == NIN * NOUT * DDIM * DIN)  W    = (const float*)d_in[idx];
        else if (in_sizes[idx] == NOUT * DDIM)              bias = (const float*)d_in[idx];
    }
    k1_uhat<<<NIN, 320>>>(x, W);
    k2_route<<<BATCH, K2_THREADS>>>(bias, (float*)d_out);
}

// round 16
// speedup vs baseline: 1.1991x; 1.0477x over previous
#include <cuda_runtime.h>
#include <cuda_fp16.h>

// Problem constants
#define BATCH 128
#define NIN   1152
#define DIN   8
#define NOUT  10
#define DDIM  16
#define FDIM  160
#define NTRI  (NIN / 3)          // 384 i-triples
#define TRIH  512                // halves per triple block (960 used + 64 pad)
#define ROWH  ((size_t)NTRI * TRIH)
#define SQ_EPS 1e-7f

#define K2_THREADS 768
#define K2_WARPS   24
#define K2_ITERS   16            // triples per warp

typedef unsigned long long ull;

// u_hat scratch, i-triple-blocked layout:
//   half index = ((b*NTRI + t)*TRIH) + q*256 + lane*8 + h
//   lane = (i%3)*10 + j (0..29; 30,31 pad), q = d/8, h = d%8
__device__ __half g_uhat[(size_t)BATCH * ROWH];

// ---------------- packed f32x2 / f16x2 helpers ------------------------------
__device__ __forceinline__ ull pk2(float lo, float hi) {
    ull r; asm("mov.b64 %0, {%1, %2};" : "=l"(r) : "f"(lo), "f"(hi)); return r;
}
__device__ __forceinline__ void upk2(ull v, float& lo, float& hi) {
    asm("mov.b64 {%0, %1}, %2;" : "=f"(lo), "=f"(hi) : "l"(v));
}
__device__ __forceinline__ ull fma2(ull a, ull b, ull c) {
    ull d; asm("fma.rn.f32x2 %0, %1, %2, %3;" : "=l"(d) : "l"(a), "l"(b), "l"(c)); return d;
}
__device__ __forceinline__ ull mul2(ull a, ull b) {
    ull d; asm("mul.rn.f32x2 %0, %1, %2;" : "=l"(d) : "l"(a), "l"(b)); return d;
}
__device__ __forceinline__ ull add2(ull a, ull b) {
    ull d; asm("add.rn.f32x2 %0, %1, %2;" : "=l"(d) : "l"(a), "l"(b)); return d;
}
__device__ __forceinline__ unsigned hadd2u(unsigned a, unsigned b) {
    unsigned d; asm("add.rn.f16x2 %0, %1, %2;" : "=r"(d) : "r"(a), "r"(b)); return d;
}
__device__ __forceinline__ unsigned hfma2u(unsigned a, unsigned b, unsigned c) {
    unsigned d; asm("fma.rn.f16x2 %0, %1, %2, %3;" : "=r"(d) : "r"(a), "r"(b), "r"(c)); return d;
}
__device__ __forceinline__ ull h2_to_f2(unsigned h2) {
    ull r;
    asm("{\n\t"
        ".reg .b16 l, h;\n\t"
        ".reg .f32 fl, fh;\n\t"
        "mov.b32 {l, h}, %1;\n\t"
        "cvt.f32.f16 fl, l;\n\t"
        "cvt.f32.f16 fh, h;\n\t"
        "mov.b64 %0, {fl, fh};\n\t"
        "}" : "=l"(r) : "r"(h2));
    return r;
}
__device__ __forceinline__ unsigned f2_to_h2(float lo, float hi) {
    const __half2 h = __floats2half2_rn(lo, hi);
    return *reinterpret_cast<const unsigned*>(&h);
}

// ---------------------------------------------------------------------------
// K1: u_hat[b,i,f] = sum_k W[i,f,k] * x[b,i,k]  -> fp16, triple-blocked store.
// (EXACT R7 kernel — best measured k1; do not modify)
// ---------------------------------------------------------------------------
__global__ __launch_bounds__(320) void k1_uhat(const float* __restrict__ x,
                                               const float* __restrict__ W) {
    const int i = blockIdx.x;                 // 0..1151
    const int t = i / 3;
    const int g = i % 3;
    __shared__ __align__(16) float Ws[FDIM * DIN];   // 5 KB
    __shared__ __align__(16) float xs[BATCH * DIN];  // 4 KB
    const int tid = threadIdx.x;

    for (int tt = tid; tt < FDIM * DIN; tt += 320)
        Ws[tt] = W[(size_t)i * (FDIM * DIN) + tt];
    for (int tt = tid; tt < BATCH * DIN; tt += 320) {
        const int b = tt / DIN, k = tt % DIN;
        xs[tt] = x[((size_t)b * NIN + i) * DIN + k];
    }
    __syncthreads();

    const int f2 = tid % 80;
    const int b0 = tid / 80;
    const int j  = f2 / 8;
    const int dA = (f2 % 8) * 2;
    const int q  = dA >> 3;
    const int hh = dA & 7;

    float wA[DIN], wB[DIN];
#pragma unroll
    for (int k = 0; k < DIN; k++) {
        wA[k] = Ws[(2 * f2) * DIN + k];
        wB[k] = Ws[(2 * f2 + 1) * DIN + k];
    }

    const size_t slot_h2 = ((size_t)t * TRIH + q * 256 + (g * 10 + j) * 8 + hh) / 2;
    __half2* __restrict__ uh2 = reinterpret_cast<__half2*>(g_uhat) + slot_h2;

    for (int b = b0; b < BATCH; b += 4) {
        const float4 xa = *reinterpret_cast<const float4*>(&xs[b * DIN]);
        const float4 xb = *reinterpret_cast<const float4*>(&xs[b * DIN + 4]);
        float a0 = wA[0] * xa.x, a1 = wB[0] * xa.x;
        a0 = fmaf(wA[1], xa.y, a0);  a1 = fmaf(wB[1], xa.y, a1);
        a0 = fmaf(wA[2], xa.z, a0);  a1 = fmaf(wB[2], xa.z, a1);
        a0 = fmaf(wA[3], xa.w, a0);  a1 = fmaf(wB[3], xa.w, a1);
        a0 = fmaf(wA[4], xb.x, a0);  a1 = fmaf(wB[4], xb.x, a1);
        a0 = fmaf(wA[5], xb.y, a0);  a1 = fmaf(wB[5], xb.y, a1);
        a0 = fmaf(wA[6], xb.z, a0);  a1 = fmaf(wB[6], xb.z, a1);
        a0 = fmaf(wA[7], xb.w, a0);  a1 = fmaf(wB[7], xb.w, a1);
        uh2[(size_t)b * (ROWH / 2)] = __floats2half2_rn(a0, a1);
    }
}

// ---------------------------------------------------------------------------
// K2: fused 3-iteration dynamic routing, one block (768 thr) per b.
// Pass 0: fp16 HADD2 accumulation.  Pass 1: fp16 HFMA2 dot + accumulate
// (v1 is second-order on output).  Pass 2: f32 (output path).
// ---------------------------------------------------------------------------
__global__ __launch_bounds__(K2_THREADS) void k2_route(const float* __restrict__ bias,
                                                       float* __restrict__ out) {
    const int b   = blockIdx.x;
    const int tid = threadIdx.x;
    const int w   = tid >> 5;
    const int l   = tid & 31;
    const bool active = (l < 30);
    const int g = active ? (l / 10) : 0;
    const int j = active ? (l % 10) : 0;
    const int leader = g * 10;

    __shared__ float s_part[K2_WARPS][FDIM];
    __shared__ float s_red[FDIM];
    __shared__ float vsum_sm[FDIM];
    __shared__ float vlast_sm[FDIM];
    __shared__ float bias_sm[FDIM];

    if (tid < FDIM) bias_sm[tid] = bias[tid];

    const uint4* __restrict__ ubase4 =
        reinterpret_cast<const uint4*>(g_uhat + (size_t)b * ROWH);
    const unsigned FULL = 0xFFFFFFFFu;

    // ================= pass 0: s0 = (1/10) * sum_i u + bias ================
    {
        unsigned ha[8], hb[8];
#pragma unroll
        for (int m = 0; m < 8; m++) { ha[m] = 0u; hb[m] = 0u; }

        uint4 p0, p1;
        {
            const uint4* up = ubase4 + (size_t)(w * K2_ITERS) * 64 + l;
            p0 = up[0];
            p1 = up[32];
        }
        for (int it = 0; it < K2_ITERS; ++it) {
            uint4 n0, n1;
            if (it + 1 < K2_ITERS) {
                const uint4* up = ubase4 + (size_t)(w * K2_ITERS + it + 1) * 64 + l;
                n0 = up[0];
                n1 = up[32];
            } else {
                n0 = p0; n1 = p1;
            }
            if ((it & 1) == 0) {
                ha[0] = hadd2u(ha[0], p0.x); ha[1] = hadd2u(ha[1], p0.y);
                ha[2] = hadd2u(ha[2], p0.z); ha[3] = hadd2u(ha[3], p0.w);
                ha[4] = hadd2u(ha[4], p1.x); ha[5] = hadd2u(ha[5], p1.y);
                ha[6] = hadd2u(ha[6], p1.z); ha[7] = hadd2u(ha[7], p1.w);
            } else {
                hb[0] = hadd2u(hb[0], p0.x); hb[1] = hadd2u(hb[1], p0.y);
                hb[2] = hadd2u(hb[2], p0.z); hb[3] = hadd2u(hb[3], p0.w);
                hb[4] = hadd2u(hb[4], p1.x); hb[5] = hadd2u(hb[5], p1.y);
                hb[6] = hadd2u(hb[6], p1.z); hb[7] = hadd2u(hb[7], p1.w);
            }
            p0 = n0; p1 = n1;
        }

        ull sacc2[8];
#pragma unroll
        for (int m = 0; m < 8; m++)
            sacc2[m] = add2(h2_to_f2(ha[m]), h2_to_f2(hb[m]));

#pragma unroll
        for (int m = 0; m < 8; m++) {
            const ull t1 = __shfl_down_sync(FULL, sacc2[m], 10);
            const ull t2 = __shfl_down_sync(FULL, sacc2[m], 20);
            sacc2[m] = add2(sacc2[m], add2(t1, t2));
        }
        if (l < NOUT) {
#pragma unroll
            for (int m = 0; m < 8; m++)
                *reinterpret_cast<ull*>(&s_part[w][l * DDIM + 2 * m]) = sacc2[m];
        }
        __syncthreads();

        if (tid < FDIM) {
            float acc = 0.f;
#pragma unroll
            for (int ww = 0; ww < K2_WARPS; ww++) acc += s_part[ww][tid];
            s_red[tid] = acc * (1.0f / NOUT) + bias_sm[tid];
        }
        __syncthreads();

        if (tid < NOUT) {
            float sv[DDIM];
            float sq = 0.f;
#pragma unroll
            for (int d = 0; d < DDIM; d++) {
                sv[d] = s_red[tid * DDIM + d];
                sq = fmaf(sv[d], sv[d], sq);
            }
            const float scale = sq / (1.0f + sq) * rsqrtf(sq + SQ_EPS);
#pragma unroll
            for (int d = 0; d < DDIM; d++)
                vsum_sm[tid * DDIM + d] = scale * sv[d];   // v0
        }
        __syncthreads();
    }

    // ================= pass 1: fp16 dot + fp16 accumulate ==================
    {
        unsigned vh[8];
#pragma unroll
        for (int m = 0; m < 8; m++)
            vh[m] = f2_to_h2(vsum_sm[j * DDIM + 2 * m], vsum_sm[j * DDIM + 2 * m + 1]);
        unsigned hA[8], hB[8];
#pragma unroll
        for (int m = 0; m < 8; m++) { hA[m] = 0u; hB[m] = 0u; }

        uint4 p0, p1;
        {
            const uint4* up = ubase4 + (size_t)(w * K2_ITERS) * 64 + l;
            p0 = up[0];
            p1 = up[32];
        }
        for (int it = 0; it < K2_ITERS; ++it) {
            uint4 n0, n1;
            if (it + 1 < K2_ITERS) {
                const uint4* up = ubase4 + (size_t)(w * K2_ITERS + it + 1) * 64 + l;
                n0 = up[0];
                n1 = up[32];
            } else {
                n0 = p0; n1 = p1;
            }

            // fp16 dot: two independent HFMA2 chains
            unsigned da = hfma2u(p0.x, vh[0], 0u);
            unsigned db = hfma2u(p0.y, vh[1], 0u);
            da = hfma2u(p0.z, vh[2], da);
            db = hfma2u(p0.w, vh[3], db);
            da = hfma2u(p1.x, vh[4], da);
            db = hfma2u(p1.y, vh[5], db);
            da = hfma2u(p1.z, vh[6], da);
            db = hfma2u(p1.w, vh[7], db);
            const unsigned dd = hadd2u(da, db);
            float alo, ahi; upk2(h2_to_f2(dd), alo, ahi);
            float a = alo + ahi;
            a = fmaxf(fminf(a, 60.f), -60.f);
            const float e = active ? __expf(a) : 0.f;

            const float p  = e + __shfl_down_sync(FULL, e, 5);
            const float qq = p + __shfl_down_sync(FULL, p, 2);
            const float r  = qq + __shfl_down_sync(FULL, qq, 1);
            const float es = r + __shfl_down_sync(FULL, p, 4);
            const float esum = __shfl_sync(FULL, es, leader);
            const float c = __fdividef(e, esum);
            const unsigned ch = f2_to_h2(c, c);

            if ((it & 1) == 0) {
                hA[0] = hfma2u(ch, p0.x, hA[0]); hA[1] = hfma2u(ch, p0.y, hA[1]);
                hA[2] = hfma2u(ch, p0.z, hA[2]); hA[3] = hfma2u(ch, p0.w, hA[3]);
                hA[4] = hfma2u(ch, p1.x, hA[4]); hA[5] = hfma2u(ch, p1.y, hA[5]);
                hA[6] = hfma2u(ch, p1.z, hA[6]); hA[7] = hfma2u(ch, p1.w, hA[7]);
            } else {
                hB[0] = hfma2u(ch, p0.x, hB[0]); hB[1] = hfma2u(ch, p0.y, hB[1]);
                hB[2] = hfma2u(ch, p0.z, hB[2]); hB[3] = hfma2u(ch, p0.w, hB[3]);
                hB[4] = hfma2u(ch, p1.x, hB[4]); hB[5] = hfma2u(ch, p1.y, hB[5]);
                hB[6] = hfma2u(ch, p1.z, hB[6]); hB[7] = hfma2u(ch, p1.w, hB[7]);
            }
            p0 = n0; p1 = n1;
        }

        ull sacc2[8];
#pragma unroll
        for (int m = 0; m < 8; m++)
            sacc2[m] = add2(h2_to_f2(hA[m]), h2_to_f2(hB[m]));

#pragma unroll
        for (int m = 0; m < 8; m++) {
            const ull t1 = __shfl_down_sync(FULL, sacc2[m], 10);
            const ull t2 = __shfl_down_sync(FULL, sacc2[m], 20);
            sacc2[m] = add2(sacc2[m], add2(t1, t2));
        }
        if (l < NOUT) {
#pragma unroll
            for (int m = 0; m < 8; m++)
                *reinterpret_cast<ull*>(&s_part[w][l * DDIM + 2 * m]) = sacc2[m];
        }
        __syncthreads();

        if (tid < FDIM) {
            float acc = 0.f;
#pragma unroll
            for (int ww = 0; ww < K2_WARPS; ww++) acc += s_part[ww][tid];
            s_red[tid] = acc + bias_sm[tid];
        }
        __syncthreads();

        if (tid < NOUT) {
            float sv[DDIM];
            float sq = 0.f;
#pragma unroll
            for (int d = 0; d < DDIM; d++) {
                sv[d] = s_red[tid * DDIM + d];
                sq = fmaf(sv[d], sv[d], sq);
            }
            const float scale = sq / (1.0f + sq) * rsqrtf(sq + SQ_EPS);
#pragma unroll
            for (int d = 0; d < DDIM; d++)
                vsum_sm[tid * DDIM + d] += scale * sv[d];   // += v1
        }
        __syncthreads();
    }

    // ================= pass 2: f32 (output path) ===========================
    {
        ull vr2[8];
#pragma unroll
        for (int m = 0; m < 8; m++)
            vr2[m] = pk2(vsum_sm[j * DDIM + 2 * m], vsum_sm[j * DDIM + 2 * m + 1]);
        ull sacc2[8];
#pragma unroll
        for (int m = 0; m < 8; m++) sacc2[m] = 0ull;

        uint4 p0, p1;
        {
            const uint4* up = ubase4 + (size_t)(w * K2_ITERS) * 64 + l;
            p0 = up[0];
            p1 = up[32];
        }
        for (int it = 0; it < K2_ITERS; ++it) {
            uint4 n0, n1;
            if (it + 1 < K2_ITERS) {
                const uint4* up = ubase4 + (size_t)(w * K2_ITERS + it + 1) * 64 + l;
                n0 = up[0];
                n1 = up[32];
            } else {
                n0 = p0; n1 = p1;
            }

            ull u2[8];
            u2[0] = h2_to_f2(p0.x); u2[1] = h2_to_f2(p0.y);
            u2[2] = h2_to_f2(p0.z); u2[3] = h2_to_f2(p0.w);
            u2[4] = h2_to_f2(p1.x); u2[5] = h2_to_f2(p1.y);
            u2[6] = h2_to_f2(p1.z); u2[7] = h2_to_f2(p1.w);

            ull a2a = mul2(u2[0], vr2[0]);
            ull a2b = mul2(u2[1], vr2[1]);
            a2a = fma2(u2[2], vr2[2], a2a);
            a2b = fma2(u2[3], vr2[3], a2b);
            a2a = fma2(u2[4], vr2[4], a2a);
            a2b = fma2(u2[5], vr2[5], a2b);
            a2a = fma2(u2[6], vr2[6], a2a);
            a2b = fma2(u2[7], vr2[7], a2b);
            const ull a2 = add2(a2a, a2b);
            float alo, ahi; upk2(a2, alo, ahi);
            float a = alo + ahi;
            a = fmaxf(fminf(a, 60.f), -60.f);
            const float e = active ? __expf(a) : 0.f;

            const float p  = e + __shfl_down_sync(FULL, e, 5);
            const float qq = p + __shfl_down_sync(FULL, p, 2);
            const float r  = qq + __shfl_down_sync(FULL, qq, 1);
            const float es = r + __shfl_down_sync(FULL, p, 4);
            const float esum = __shfl_sync(FULL, es, leader);
            const float c = __fdividef(e, esum);
            const ull c2 = pk2(c, c);
#pragma unroll
            for (int m = 0; m < 8; m++) sacc2[m] = fma2(c2, u2[m], sacc2[m]);

            p0 = n0; p1 = n1;
        }

#pragma unroll
        for (int m = 0; m < 8; m++) {
            const ull t1 = __shfl_down_sync(FULL, sacc2[m], 10);
            const ull t2 = __shfl_down_sync(FULL, sacc2[m], 20);
            sacc2[m] = add2(sacc2[m], add2(t1, t2));
        }
        if (l < NOUT) {
#pragma unroll
            for (int m = 0; m < 8; m++)
                *reinterpret_cast<ull*>(&s_part[w][l * DDIM + 2 * m]) = sacc2[m];
        }
        __syncthreads();

        if (tid < FDIM) {
            float acc = 0.f;
#pragma unroll
            for (int ww = 0; ww < K2_WARPS; ww++) acc += s_part[ww][tid];
            s_red[tid] = acc + bias_sm[tid];
        }
        __syncthreads();

        if (tid < NOUT) {
            float sv[DDIM];
            float sq = 0.f;
#pragma unroll
            for (int d = 0; d < DDIM; d++) {
                sv[d] = s_red[tid * DDIM + d];
                sq = fmaf(sv[d], sv[d], sq);
            }
            const float scale = sq / (1.0f + sq) * rsqrtf(sq + SQ_EPS);
#pragma unroll
            for (int d = 0; d < DDIM; d++)
                vlast_sm[tid * DDIM + d] = scale * sv[d];   // v2 (output)
        }
        __syncthreads();
    }

    if (tid < FDIM) out[(size_t)b * FDIM + tid] = vlast_sm[tid];
}

// ---------------------------------------------------------------------------
extern "C" void kernel_launch(void* const* d_in, const int* in_sizes, int n_in,
                              void* d_out, int out_size) {
    const float* x = nullptr;
    const float* W = nullptr;
    const float* bias = nullptr;
    for (int idx = 0; idx < n_in; ++idx) {
        if (in_sizes[idx] == BATCH * NIN * DIN)             x    = (const float*)d_in[idx];
        else if (in_sizes[idx] == NIN * NOUT * DDIM * DIN)  W    = (const float*)d_in[idx];
        else if (in_sizes[idx] == NOUT * DDIM)              bias = (const float*)d_in[idx];
    }
    k1_uhat<<<NIN, 320>>>(x, W);
    k2_route<<<BATCH, K2_THREADS>>>(bias, (float*)d_out);
}